// round 11
// baseline (speedup 1.0000x reference)
#include <cuda_runtime.h>
#include <cuda_fp16.h>
#include <math.h>
#include <stdint.h>

#define BSZ 4
#define SEQ 2048
#define HID 1024
#define NHD 16
#define DH  64
#define TOK (BSZ*SEQ)   // 8192

// Scratch: plain row-major fp16 operands (pre-rounded; no permutation).
__device__ __half g_q  [(size_t)TOK*HID];
__device__ __half g_ln [(size_t)TOK*HID];
__device__ __half g_kr [(size_t)TOK*HID];
__device__ __half g_vr [(size_t)TOK*HID];
__device__ __half g_cr [(size_t)TOK*HID];
__device__ __half g_wq [(size_t)3*HID*HID];
__device__ __half g_wo [(size_t)HID*HID];

// ===========================================================================
// helpers
// ===========================================================================
__device__ __forceinline__ uint32_t s2u(const void* p) {
    uint32_t a;
    asm("{ .reg .u64 t; cvta.to.shared.u64 t, %1; cvt.u32.u64 %0, t; }"
        : "=r"(a) : "l"(p));
    return a;
}
__device__ __forceinline__ uint32_t h2(float hi, float lo) {
    uint32_t r;
    asm("cvt.rn.f16x2.f32 %0, %1, %2;" : "=r"(r) : "f"(hi), "f"(lo));
    return r;
}
// D += A*B, m16n8k16 f16 (f32 accum)
__device__ __forceinline__ void mma_f16(float* d, const uint32_t* a, const uint32_t* b) {
    asm volatile(
        "mma.sync.aligned.m16n8k16.row.col.f32.f16.f16.f32 "
        "{%0,%1,%2,%3}, {%4,%5,%6,%7}, {%8,%9}, {%0,%1,%2,%3};"
        : "+f"(d[0]), "+f"(d[1]), "+f"(d[2]), "+f"(d[3])
        : "r"(a[0]), "r"(a[1]), "r"(a[2]), "r"(a[3]), "r"(b[0]), "r"(b[1]));
}
__device__ __forceinline__ void ldsm4(uint32_t& r0, uint32_t& r1,
                                      uint32_t& r2, uint32_t& r3, uint32_t a) {
    asm volatile("ldmatrix.sync.aligned.m8n8.x4.shared.b16 {%0,%1,%2,%3}, [%4];"
                 : "=r"(r0), "=r"(r1), "=r"(r2), "=r"(r3) : "r"(a));
}
__device__ __forceinline__ void ldsm4t(uint32_t& r0, uint32_t& r1,
                                       uint32_t& r2, uint32_t& r3, uint32_t a) {
    asm volatile("ldmatrix.sync.aligned.m8n8.x4.trans.shared.b16 {%0,%1,%2,%3}, [%4];"
                 : "=r"(r0), "=r"(r1), "=r"(r2), "=r"(r3) : "r"(a));
}
#define CP_ASYNC16(dst, src) \
    asm volatile("cp.async.cg.shared.global [%0], [%1], 16;" :: "r"(dst), "l"(src))
#define CP_COMMIT() asm volatile("cp.async.commit_group;" ::: "memory")
#define CP_WAIT(n)  asm volatile("cp.async.wait_group %0;" :: "n"(n) : "memory")

// ===========================================================================
// Kernel 0: round f32 -> fp16 (plain layout)
// ===========================================================================
__global__ __launch_bounds__(256) void round16_kernel(const float* __restrict__ src,
                                                      __half* __restrict__ dst, int n4)
{
    int i = blockIdx.x * blockDim.x + threadIdx.x;
    if (i < n4) {
        float4 v = reinterpret_cast<const float4*>(src)[i];
        uint2 u = {h2(v.y, v.x), h2(v.w, v.z)};
        *reinterpret_cast<uint2*>(dst + 4 * i) = u;
    }
}

// ===========================================================================
// Kernel 1: LayerNorm -> g_ln (fp16 plain)
// ===========================================================================
__global__ __launch_bounds__(256) void ln_kernel(const float* __restrict__ x,
                                                 const float* __restrict__ w,
                                                 const float* __restrict__ bb,
                                                 __half* __restrict__ y)
{
    int row = blockIdx.x;
    int t = threadIdx.x;
    float4 v = reinterpret_cast<const float4*>(x + (size_t)row * HID)[t];
    float s = v.x + v.y + v.z + v.w;
    float q = v.x*v.x + v.y*v.y + v.z*v.z + v.w*v.w;
#pragma unroll
    for (int o = 16; o > 0; o >>= 1) {
        s += __shfl_xor_sync(0xffffffffu, s, o);
        q += __shfl_xor_sync(0xffffffffu, q, o);
    }
    __shared__ float ss[8], sq[8], smu, srs;
    if ((t & 31) == 0) { ss[t >> 5] = s; sq[t >> 5] = q; }
    __syncthreads();
    if (t == 0) {
        float S = 0.f, Q2 = 0.f;
#pragma unroll
        for (int i = 0; i < 8; i++) { S += ss[i]; Q2 += sq[i]; }
        float mu = S * (1.0f / HID);
        smu = mu;
        srs = rsqrtf(Q2 * (1.0f / HID) - mu * mu + 1e-12f);
    }
    __syncthreads();
    float mu = smu, rs = srs;
    float4 w4 = reinterpret_cast<const float4*>(w)[t];
    float4 b4 = reinterpret_cast<const float4*>(bb)[t];
    float o0 = (v.x - mu) * rs * w4.x + b4.x;
    float o1 = (v.y - mu) * rs * w4.y + b4.y;
    float o2 = (v.z - mu) * rs * w4.z + b4.z;
    float o3 = (v.w - mu) * rs * w4.w + b4.w;
    uint2 u = {h2(o1, o0), h2(o3, o2)};
    *reinterpret_cast<uint2*>(y + (size_t)row * HID + 4 * t) = u;
}

// ===========================================================================
// Kernel 2/4: fp16 mma GEMM  C[M,N] = A[M,K] * W[N,K]^T
//   128x128 CTA, 256 thr, 8 warps (4M x 2N), warp 32x64.
//   BK=64, 2-stage cp.async, row stride 72 halves (144B: 16i mod 128 distinct
//   -> conflict-free ldmatrix). All fragments via ldmatrix.x4.
// ===========================================================================
#define GSTRH 72
#define GTILEH (128*GSTRH)          // 9216 halves / tile
#define GSSH   (2*GTILEH)           // 18432 halves / stage
#define GSS_B  (GSSH*2)             // 36864 B / stage
#define GEMM_SMEM (2*GSS_B)         // 73728 B -> 2 CTAs/SM

template<int MODE>
__global__ __launch_bounds__(256, 2) void gemm_mma(
    const __half* __restrict__ Ap, const __half* __restrict__ W,
    const float* __restrict__ bias,
    __half* __restrict__ outq,
    float* __restrict__ outk, __half* __restrict__ outkr,
    float* __restrict__ outv, __half* __restrict__ outvr,
    float* __restrict__ outp)
{
    extern __shared__ __half smh[];
    const uint32_t smb = s2u(smh);

    const int tid = threadIdx.x;
    const int wid = tid >> 5, lane = tid & 31;
    const int g = lane >> 2, tig = lane & 3;
    const int wM = wid & 3, wN = wid >> 2;
    const int m0 = blockIdx.x * 128, n0 = blockIdx.y * 128;
    const int NT = HID / 64;   // 16

    float acc[2][8][4];
#pragma unroll
    for (int a = 0; a < 2; a++)
#pragma unroll
        for (int b = 0; b < 8; b++)
#pragma unroll
            for (int c = 0; c < 4; c++) acc[a][b][c] = 0.f;

    // hoisted cp.async pointers: 8 chunks/thread (A:4, B:4)
    const __half* pS[8];
    uint32_t dS[8];
    {
        int row = tid >> 3, c = tid & 7;
#pragma unroll
        for (int j = 0; j < 4; j++) {
            pS[j]     = Ap + (size_t)(m0 + row + 32*j) * HID + c * 8;
            dS[j]     = (uint32_t)((row + 32*j) * GSTRH + c * 8) * 2;
            pS[j + 4] = W  + (size_t)(n0 + row + 32*j) * HID + c * 8;
            dS[j + 4] = (uint32_t)(GTILEH + (row + 32*j) * GSTRH + c * 8) * 2;
        }
    }
    auto load_stage = [&](int s, int kt) {
        uint32_t base = smb + (uint32_t)s * GSS_B;
#pragma unroll
        for (int j = 0; j < 8; j++)
            CP_ASYNC16(base + dS[j], pS[j] + kt * 64);
    };

    // hoisted ldmatrix base addresses (stage 0, ks 0)
    const int lq = lane >> 3, lr = lane & 7;
    uint32_t aA[2], aB[4];
#pragma unroll
    for (int mt = 0; mt < 2; mt++) {
        int row = wM * 32 + mt * 16 + (lq & 1) * 8 + lr;
        aA[mt] = smb + (uint32_t)(row * GSTRH + (lq >> 1) * 8) * 2;
    }
#pragma unroll
    for (int p = 0; p < 4; p++) {
        int row = wN * 64 + 16 * p + (lq & 1) * 8 + lr;
        aB[p] = smb + (uint32_t)(GTILEH + row * GSTRH + (lq >> 1) * 8) * 2;
    }

    load_stage(0, 0); CP_COMMIT();
    load_stage(1, 1); CP_COMMIT();

    for (int kt = 0; kt < NT; kt++) {
        CP_WAIT(1);
        __syncthreads();
        const uint32_t sb = (uint32_t)(kt & 1) * GSS_B;
#pragma unroll
        for (int ks = 0; ks < 4; ks++) {
            const uint32_t ko = sb + ks * 32;      // ks*16 halves
            uint32_t af[2][4], bf[8][2];
#pragma unroll
            for (int mt = 0; mt < 2; mt++)
                ldsm4(af[mt][0], af[mt][1], af[mt][2], af[mt][3], aA[mt] + ko);
#pragma unroll
            for (int p = 0; p < 4; p++)
                ldsm4(bf[2*p][0], bf[2*p+1][0], bf[2*p][1], bf[2*p+1][1], aB[p] + ko);
#pragma unroll
            for (int mt = 0; mt < 2; mt++)
#pragma unroll
                for (int nt = 0; nt < 8; nt++)
                    mma_f16(acc[mt][nt], af[mt], bf[nt]);
        }
        __syncthreads();
        if (kt + 2 < NT) load_stage(kt & 1, kt + 2);
        CP_COMMIT();
    }

    // ---- epilogue (plain layouts everywhere)
#pragma unroll
    for (int nt = 0; nt < 8; nt++) {
        int cb = n0 + wN * 64 + nt * 8 + 2 * tig;
        float2 bv = {0.f, 0.f};
        int seg = 0, col = cb;
        if (MODE == 0) {
            bv = *reinterpret_cast<const float2*>(bias + cb);
            seg = cb >> 10;
            col = cb & 1023;
        }
#pragma unroll
        for (int mt = 0; mt < 2; mt++) {
            int r = m0 + wM * 32 + mt * 16 + g;
#pragma unroll
            for (int hh = 0; hh < 2; hh++) {
                size_t roff = (size_t)(r + hh * 8) * HID;
                float2 v = {acc[mt][nt][2*hh+0] + bv.x, acc[mt][nt][2*hh+1] + bv.y};
                if (MODE == 0) {
                    uint32_t u = h2(v.y, v.x);
                    if (seg == 0) {
                        *reinterpret_cast<uint32_t*>(outq + roff + col) = u;
                    } else if (seg == 1) {
                        *reinterpret_cast<float2*>(outk + roff + col) = v;
                        *reinterpret_cast<uint32_t*>(outkr + roff + col) = u;
                    } else {
                        *reinterpret_cast<float2*>(outv + roff + col) = v;
                        *reinterpret_cast<uint32_t*>(outvr + roff + col) = u;
                    }
                } else {
                    *reinterpret_cast<float2*>(outp + roff + col) = v;
                }
            }
        }
    }
}

// ===========================================================================
// Kernel 3: flash attention, fp16 mma, 2-stage cp.async KV pipeline.
//   K fragments via ldmatrix (non-trans), V via ldmatrix.trans; both stride 72.
//   P lives in registers. Q fragments from global (plain layout), once.
//   stage: K[64][72] | V[64][72] halves (18432 B) ; mask f32 at 18432.
// ===========================================================================
#define AKSTR 72
#define AVSTR 72
#define AVOFF (64*AKSTR)                    // 4608 halves
#define ASTG_B 18688                        // 18432 + 256 mask
#define ATT_SMEM (2*ASTG_B)                 // 37376 B

__global__ __launch_bounds__(256) void attn_mma(
    const __half* __restrict__ Qp, const __half* __restrict__ Kp,
    const __half* __restrict__ Vp, const float* __restrict__ mask,
    float* __restrict__ ctx, __half* __restrict__ ctxr)
{
    extern __shared__ __half smh[];
    const uint32_t smb = s2u(smh);

    const int tid = threadIdx.x;
    const int wid = tid >> 5, lane = tid & 31;
    const int g = lane >> 2, tig = lane & 3;
    const int q0 = blockIdx.x * 128;
    const int h  = blockIdx.y;
    const int b  = blockIdx.z;
    const int NT = SEQ / 64;   // 32
    const int pr = wid * 16;

    const __half* qbase = Qp + (size_t)b * SEQ * HID + h * DH;
    const __half* kbase = Kp + (size_t)b * SEQ * HID + h * DH;
    const __half* vbase = Vp + (size_t)b * SEQ * HID + h * DH;
    const float*  maskb = mask + (size_t)b * SEQ;

    const float L2E = 1.4426950408889634f;
    const float SCL = 0.125f * L2E;

    // hoisted cp.async pointers: K 2 + V 2 chunks / thread + mask
    const __half* pK[2]; const __half* pV[2];
    uint32_t dK[2], dV[2];
    {
        int row = tid >> 3, c = tid & 7;
#pragma unroll
        for (int j = 0; j < 2; j++) {
            pK[j] = kbase + (size_t)(row + 32*j) * HID + c * 8;
            dK[j] = (uint32_t)((row + 32*j) * AKSTR + c * 8) * 2;
            pV[j] = vbase + (size_t)(row + 32*j) * HID + c * 8;
            dV[j] = (uint32_t)(AVOFF + (row + 32*j) * AVSTR + c * 8) * 2;
        }
    }
    const size_t KADV = (size_t)64 * HID;
    auto issue_tile = [&](int nt) {
        uint32_t base = smb + (uint32_t)(nt & 1) * ASTG_B;
#pragma unroll
        for (int j = 0; j < 2; j++) {
            CP_ASYNC16(base + dK[j], pK[j] + nt * KADV);
            CP_ASYNC16(base + dV[j], pV[j] + nt * KADV);
        }
        if (tid < 16)
            CP_ASYNC16(base + 18432 + tid * 16, maskb + nt * 64 + tid * 4);
    };

    issue_tile(0); CP_COMMIT();
    issue_tile(1); CP_COMMIT();

    // ---- Q fragments from global (plain layout)
    uint32_t qf[4][4];
    {
        const __half* q0p = qbase + (size_t)(q0 + pr + g) * HID + 2 * tig;
        const __half* q1p = q0p + (size_t)8 * HID;
#pragma unroll
        for (int j = 0; j < 4; j++) {
            qf[j][0] = *reinterpret_cast<const uint32_t*>(q0p + j * 16);
            qf[j][1] = *reinterpret_cast<const uint32_t*>(q1p + j * 16);
            qf[j][2] = *reinterpret_cast<const uint32_t*>(q0p + j * 16 + 8);
            qf[j][3] = *reinterpret_cast<const uint32_t*>(q1p + j * 16 + 8);
        }
    }

    // hoisted ldmatrix base addresses
    const int lq = lane >> 3, lr = lane & 7;
    uint32_t aK[4];
#pragma unroll
    for (int p = 0; p < 4; p++) {
        int row = 16 * p + (lq & 1) * 8 + lr;
        aK[p] = smb + (uint32_t)(row * AKSTR + (lq >> 1) * 8) * 2;
    }
    const int rbase = (lane & 7) + 8 * ((lane >> 3) & 1);
    const int cbase = 8 * (lane >> 4);
    const uint32_t aV0 = smb + (uint32_t)(AVOFF + rbase * AVSTR + cbase) * 2;

    float m0r = -1e30f, m1r = -1e30f, l0 = 0.f, l1 = 0.f;
    float oacc[8][4];
#pragma unroll
    for (int i = 0; i < 8; i++)
#pragma unroll
        for (int j = 0; j < 4; j++) oacc[i][j] = 0.f;

    for (int nt = 0; nt < NT; nt++) {
        CP_WAIT(1);
        __syncthreads();
        const uint32_t sb = (uint32_t)(nt & 1) * ASTG_B;
        const float* Ms = reinterpret_cast<const float*>(
            reinterpret_cast<const char*>(smh) + sb + 18432);

        // ---- S = Q K^T  (K B-frags via ldmatrix)
        float sf[8][4];
#pragma unroll
        for (int i = 0; i < 8; i++)
#pragma unroll
            for (int j = 0; j < 4; j++) sf[i][j] = 0.f;
#pragma unroll
        for (int ks = 0; ks < 4; ks++) {
            const uint32_t ko = sb + ks * 32;
            uint32_t kb[8][2];
#pragma unroll
            for (int p = 0; p < 4; p++)
                ldsm4(kb[2*p][0], kb[2*p+1][0], kb[2*p][1], kb[2*p+1][1], aK[p] + ko);
#pragma unroll
            for (int sn = 0; sn < 8; sn++)
                mma_f16(sf[sn], qf[ks], kb[sn]);
        }

        // ---- online softmax (base-2 domain)
        float zmax0 = -1e30f, zmax1 = -1e30f;
#pragma unroll
        for (int sn = 0; sn < 8; sn++) {
            float mc0 = Ms[sn * 8 + 2 * tig]     * L2E;
            float mc1 = Ms[sn * 8 + 2 * tig + 1] * L2E;
            sf[sn][0] = sf[sn][0] * SCL + mc0;
            sf[sn][1] = sf[sn][1] * SCL + mc1;
            sf[sn][2] = sf[sn][2] * SCL + mc0;
            sf[sn][3] = sf[sn][3] * SCL + mc1;
            zmax0 = fmaxf(zmax0, fmaxf(sf[sn][0], sf[sn][1]));
            zmax1 = fmaxf(zmax1, fmaxf(sf[sn][2], sf[sn][3]));
        }
#pragma unroll
        for (int o2 = 1; o2 < 4; o2 <<= 1) {
            zmax0 = fmaxf(zmax0, __shfl_xor_sync(0xffffffffu, zmax0, o2));
            zmax1 = fmaxf(zmax1, __shfl_xor_sync(0xffffffffu, zmax1, o2));
        }
        float mn0 = fmaxf(m0r, zmax0), mn1 = fmaxf(m1r, zmax1);
        float al0 = exp2f(m0r - mn0), al1 = exp2f(m1r - mn1);
        m0r = mn0; m1r = mn1;

        float rs0 = 0.f, rs1 = 0.f;
#pragma unroll
        for (int sn = 0; sn < 8; sn++) {
            sf[sn][0] = exp2f(sf[sn][0] - mn0);
            sf[sn][1] = exp2f(sf[sn][1] - mn0);
            sf[sn][2] = exp2f(sf[sn][2] - mn1);
            sf[sn][3] = exp2f(sf[sn][3] - mn1);
            rs0 += sf[sn][0] + sf[sn][1];
            rs1 += sf[sn][2] + sf[sn][3];
        }
#pragma unroll
        for (int o2 = 1; o2 < 4; o2 <<= 1) {
            rs0 += __shfl_xor_sync(0xffffffffu, rs0, o2);
            rs1 += __shfl_xor_sync(0xffffffffu, rs1, o2);
        }
        l0 = l0 * al0 + rs0;
        l1 = l1 * al1 + rs1;
#pragma unroll
        for (int dn = 0; dn < 8; dn++) {
            oacc[dn][0] *= al0; oacc[dn][1] *= al0;
            oacc[dn][2] *= al1; oacc[dn][3] *= al1;
        }

        // ---- O += P V  (P from registers; V via ldmatrix.trans)
#pragma unroll
        for (int j = 0; j < 4; j++) {
            uint32_t pa[4];
            pa[0] = h2(sf[2*j][1],   sf[2*j][0]);
            pa[1] = h2(sf[2*j][3],   sf[2*j][2]);
            pa[2] = h2(sf[2*j+1][1], sf[2*j+1][0]);
            pa[3] = h2(sf[2*j+1][3], sf[2*j+1][2]);
            uint32_t rowa = aV0 + sb + (uint32_t)(16 * j * AVSTR) * 2;
#pragma unroll
            for (int dnp = 0; dnp < 4; dnp++) {
                uint32_t v0, v1, v2, v3;
                ldsm4t(v0, v1, v2, v3, rowa + (uint32_t)(dnp * 16) * 2);
                uint32_t vb0[2] = {v0, v1};
                uint32_t vb1[2] = {v2, v3};
                mma_f16(oacc[2*dnp],     pa, vb0);
                mma_f16(oacc[2*dnp + 1], pa, vb1);
            }
        }
        __syncthreads();
        if (nt + 2 < NT) issue_tile(nt + 2);
        CP_COMMIT();
    }

    // ---- write context: exact f32 to d_out; fp16 copy for proj GEMM
    float inv0 = 1.0f / l0, inv1 = 1.0f / l1;
    int r0 = b * SEQ + q0 + pr + g;
#pragma unroll
    for (int dn = 0; dn < 8; dn++) {
        int col = h * DH + dn * 8 + 2 * tig;
        float2 v0 = {oacc[dn][0] * inv0, oacc[dn][1] * inv0};
        float2 v1 = {oacc[dn][2] * inv1, oacc[dn][3] * inv1};
        *reinterpret_cast<float2*>(ctx + (size_t)r0 * HID + col)       = v0;
        *reinterpret_cast<float2*>(ctx + (size_t)(r0 + 8) * HID + col) = v1;
        *reinterpret_cast<uint32_t*>(ctxr + (size_t)r0 * HID + col)       = h2(v0.y, v0.x);
        *reinterpret_cast<uint32_t*>(ctxr + (size_t)(r0 + 8) * HID + col) = h2(v1.y, v1.x);
    }
}

// ===========================================================================
// Host side
// ===========================================================================
extern "C" void kernel_launch(void* const* d_in, const int* in_sizes, int n_in,
                              void* d_out, int out_size)
{
    const float* input = (const float*)d_in[0];
    const float* mask  = (const float*)d_in[1];
    const float* nw    = (const float*)d_in[2];
    const float* nb    = (const float*)d_in[3];
    const float* qkvw  = (const float*)d_in[4];
    const float* qkvb  = (const float*)d_in[5];
    const float* ow    = (const float*)d_in[6];

    float* out   = (float*)d_out;
    float* out_o = out;
    float* out_k = out + (size_t)TOK * HID;
    float* out_v = out + 2 * (size_t)TOK * HID;
    float* out_c = out + 3 * (size_t)TOK * HID;

    __half *gq, *gln, *gkr, *gvr, *gcr, *gwq, *gwo;
    cudaGetSymbolAddress((void**)&gq,  g_q);
    cudaGetSymbolAddress((void**)&gln, g_ln);
    cudaGetSymbolAddress((void**)&gkr, g_kr);
    cudaGetSymbolAddress((void**)&gvr, g_vr);
    cudaGetSymbolAddress((void**)&gcr, g_cr);
    cudaGetSymbolAddress((void**)&gwq, g_wq);
    cudaGetSymbolAddress((void**)&gwo, g_wo);

    cudaFuncSetAttribute(gemm_mma<0>, cudaFuncAttributeMaxDynamicSharedMemorySize, GEMM_SMEM);
    cudaFuncSetAttribute(gemm_mma<1>, cudaFuncAttributeMaxDynamicSharedMemorySize, GEMM_SMEM);
    cudaFuncSetAttribute(attn_mma,    cudaFuncAttributeMaxDynamicSharedMemorySize, ATT_SMEM);

    round16_kernel<<<(3*HID*HID/4 + 255)/256, 256>>>(qkvw, gwq, 3*HID*HID/4);
    round16_kernel<<<(HID*HID/4 + 255)/256, 256>>>(ow, gwo, HID*HID/4);
    ln_kernel<<<TOK, 256>>>(input, nw, nb, gln);
    gemm_mma<0><<<dim3(TOK/128, 3*HID/128), 256, GEMM_SMEM>>>(
        gln, gwq, qkvb, gq, out_k, gkr, out_v, gvr, nullptr);
    attn_mma<<<dim3(SEQ/128, NHD, BSZ), 256, ATT_SMEM>>>(gq, gkr, gvr, mask, out_c, gcr);
    gemm_mma<1><<<dim3(TOK/128, HID/128), 256, GEMM_SMEM>>>(
        gcr, gwo, nullptr, nullptr, nullptr, nullptr, nullptr, nullptr, out_o);
}